// round 15
// baseline (speedup 1.0000x reference)
#include <cuda_runtime.h>

#define BB   32
#define NN   16384
#define CKD  16
#define MAXM 8192
#define TOTCH 68

typedef unsigned long long u64t;
#define FMA2(d, a, b)  asm("fma.rn.f32x2 %0, %1, %2, %0;" : "+l"(d) : "l"(a), "l"(b))
#define PACK2(out, x)  asm("mov.b64 %0, {%1, %1};" : "=l"(out) : "f"(x))
#define UNPACK2(lo, hi, in) asm("mov.b64 {%0, %1}, %2;" : "=f"(lo), "=f"(hi) : "l"(in))

// ---------------- device scratch (static, no allocations) ----------------
__device__ __align__(256) float g_x0 [BB*MAXM*CKD];
__device__ __align__(256) float g_x1 [BB*MAXM*CKD];
__device__ __align__(256) float g_d  [BB*MAXM*CKD];
__device__ __align__(256) float g_Ud [BB*(NN-1)*CKD];
__device__ __align__(256) float g_Us [BB*(NN-1)*CKD];
__device__ __align__(256) float g_part[2ull*BB*TOTCH*64*CKD*2];
__device__ __align__(256) float g_spec[6ull*BB*4096];   // [lev][b][arr][k=2f(re)/2f+1(-im*wf)][j]
__device__ __align__(256) float g_edge[6*BB*128];       // [lev][b][d0|dmh|x0|xmh|pd|px|qd|qx]
__device__ __align__(256) float g_tabc[MAXM*64];        // [t][f] cos (deep kernel, full range)
__device__ __align__(256) float g_tabs[MAXM*64];
__device__ __align__(256) float g_tabcP[2048*64];       // [t][g] parity-permuted cos (t<2048)
__device__ __align__(256) float g_tabsP[2048*64];
__device__ __align__(256) float g_tabTP[64*2048*2];     // [g][t](cos,sin), parity-permuted (t<2048)
__device__ __align__(256) float g_wT  [6*64*16*16];     // [arr][f][i][o]

// ---------------- twiddle tables ----------------
// quarter table (rows t<2048) for dfwd/inv4 — on critical path, small
__global__ void tab_rowP_kernel() {
    int idx = blockIdx.x * blockDim.x + threadIdx.x;   // t*64 + f, t<2048
    int t = idx >> 6, f = idx & 63;
    float ph = (float)(f * t) * (2.0f / 8192.0f);
    float s, c; sincospif(ph, &s, &c);
    int g = (f & 1) ? (32 + (f >> 1)) : (f >> 1);
    g_tabcP[t * 64 + g] = c;
    g_tabsP[t * 64 + g] = s;
    g_tabTP[((size_t)g * 2048 + t) * 2 + 0] = c;
    g_tabTP[((size_t)g * 2048 + t) * 2 + 1] = s;
}
// full table for deep kernel — hidden on stream B
__global__ void tab_row_kernel() {
    int idx = blockIdx.x * blockDim.x + threadIdx.x;   // t*64 + f
    int t = idx >> 6, f = idx & 63;
    float ph = (float)(f * t) * (2.0f / 8192.0f);
    float s, c; sincospif(ph, &s, &c);
    g_tabc[idx] = c;
    g_tabs[idx] = s;
}

// ---------------- weight transpose: [i][o][f] -> [arr][f][i][o] ----------------
__global__ void wprep_kernel(const float* __restrict__ a0, const float* __restrict__ a1,
                             const float* __restrict__ a2, const float* __restrict__ a3,
                             const float* __restrict__ a4, const float* __restrict__ a5) {
    int idx = blockIdx.x * blockDim.x + threadIdx.x;
    if (idx >= 6*16384) return;
    int arr = idx >> 14;
    int r   = idx & 16383;
    int f = r >> 8, i = (r >> 4) & 15, o = r & 15;
    const float* src = (arr == 0) ? a0 : (arr == 1) ? a1 : (arr == 2) ? a2 :
                       (arr == 3) ? a3 : (arr == 4) ? a4 : a5;
    g_wT[idx] = src[(i * 16 + o) * 64 + f];
}

// =================================================================
// dfwd: fused decompose + DOUBLY-FOLDED forward truncated DFT.
// =================================================================
__global__ void __launch_bounds__(256, 2) dfwd_kernel(
        const float* __restrict__ xin, float* __restrict__ xnext,
        const float* __restrict__ ecd, const float* __restrict__ ecs,
        int m, int stride, int nchunk, int choff, int lev) {
    extern __shared__ float sm[];
    float* s_Epd = sm;
    float* s_Eqd = sm + 2048;
    float* s_Epx = sm + 4096;
    float* s_Eqx = sm + 6144;
    float* s_Opd = sm + 8192;
    float* s_Oqd = sm + 10240;
    float* s_Opx = sm + 12288;
    float* s_Oqx = sm + 14336;
    float* s_tc  = sm + 16384;
    float* s_ts  = sm + 18432;
    __shared__ float fl[64];
    int tid = threadIdx.x;
    int b0 = blockIdx.x * 4;
    int ch = blockIdx.y;
    int qm = m >> 2;
    int clen = qm / nchunk;
    int T0base = ch * clen;
    if (tid < 64) fl[tid] = (tid < 32) ? ecd[tid] : ecs[tid - 32];
    __syncthreads();

    int bloc = tid >> 6;
    int sub  = tid & 63;
    int arr  = sub >> 5;
    int lane32 = sub & 31;
    int i0 = (lane32 & 1) * 8;
    int f0 = (lane32 >> 1) * 4;
    u64t aR2[4][4] = {}, aI2[4][4] = {};

    for (int tb = 0; tb < clen; tb += 32) {
        int T0 = T0base + tb;
        {
            float4* tc4 = (float4*)s_tc;
            float4* ts4 = (float4*)s_ts;
            for (int id = tid; id < 512; id += 256) {
                int t = id >> 4, q = id & 15;
                size_t g = ((size_t)(T0 + t) * stride) * 16 + q;
                tc4[id] = ((const float4*)g_tabcP)[g];
                ts4[id] = ((const float4*)g_tabsP)[g];
            }
        }
        for (int id = tid; id < 512; id += 256) {
            int c = id & 3, t = (id >> 2) & 31, bl = id >> 7;
            int s = T0 + t;
            size_t brow = (size_t)(b0 + bl) * (2 * m);
            size_t bnext = (size_t)(b0 + bl) * m;
            int rA0 = s;
            int rB0 = (s == 0) ? (m >> 1) : (m - s);
            int rA1 = (s == 0) ? qm : ((m >> 1) - s);
            int rB1 = (s == 0) ? (3 * qm) : ((m >> 1) + s);
            float df0[4] = {0,0,0,0}, sf0[4] = {0,0,0,0}, dm0[4] = {0,0,0,0}, sm0[4] = {0,0,0,0};
            float df1[4] = {0,0,0,0}, sf1[4] = {0,0,0,0}, dm1[4] = {0,0,0,0}, sm1[4] = {0,0,0,0};
            {
                float4 F0 = *(const float4*)&xin[(brow + 2 * rA0) * 16 + c * 4];
                float4 F1 = *(const float4*)&xin[(brow + 2 * rA0 + 1) * 16 + c * 4];
                float4 M0 = *(const float4*)&xin[(brow + 2 * rB0) * 16 + c * 4];
                float4 M1 = *(const float4*)&xin[(brow + 2 * rB0 + 1) * 16 + c * 4];
                float xf[8] = {F0.x, F0.y, F0.z, F0.w, F1.x, F1.y, F1.z, F1.w};
                float xm[8] = {M0.x, M0.y, M0.z, M0.w, M1.x, M1.y, M1.z, M1.w};
#pragma unroll
                for (int p = 0; p < 8; p++) {
                    float a = xf[p], bv = xm[p];
#pragma unroll
                    for (int j = 0; j < 4; j++) {
                        df0[j] += a * fl[p * 4 + j];
                        sf0[j] += a * fl[32 + p * 4 + j];
                        dm0[j] += bv * fl[p * 4 + j];
                        sm0[j] += bv * fl[32 + p * 4 + j];
                    }
                }
                *(float4*)&xnext[(bnext + rA0) * 16 + c * 4] = make_float4(sf0[0], sf0[1], sf0[2], sf0[3]);
                *(float4*)&xnext[(bnext + rB0) * 16 + c * 4] = make_float4(sm0[0], sm0[1], sm0[2], sm0[3]);
            }
            {
                float4 F0 = *(const float4*)&xin[(brow + 2 * rA1) * 16 + c * 4];
                float4 F1 = *(const float4*)&xin[(brow + 2 * rA1 + 1) * 16 + c * 4];
                float4 M0 = *(const float4*)&xin[(brow + 2 * rB1) * 16 + c * 4];
                float4 M1 = *(const float4*)&xin[(brow + 2 * rB1 + 1) * 16 + c * 4];
                float xf[8] = {F0.x, F0.y, F0.z, F0.w, F1.x, F1.y, F1.z, F1.w};
                float xm[8] = {M0.x, M0.y, M0.z, M0.w, M1.x, M1.y, M1.z, M1.w};
#pragma unroll
                for (int p = 0; p < 8; p++) {
                    float a = xf[p], bv = xm[p];
#pragma unroll
                    for (int j = 0; j < 4; j++) {
                        df1[j] += a * fl[p * 4 + j];
                        sf1[j] += a * fl[32 + p * 4 + j];
                        dm1[j] += bv * fl[p * 4 + j];
                        sm1[j] += bv * fl[32 + p * 4 + j];
                    }
                }
                *(float4*)&xnext[(bnext + rA1) * 16 + c * 4] = make_float4(sf1[0], sf1[1], sf1[2], sf1[3]);
                *(float4*)&xnext[(bnext + rB1) * 16 + c * 4] = make_float4(sm1[0], sm1[1], sm1[2], sm1[3]);
            }
            float ped[4], pod[4], qed[4], qod[4], pex[4], pox[4], qex[4], qox[4];
            if (s == 0) {
                float* E = &g_edge[(lev * BB + (b0 + bl)) * 128];
                *(float4*)&E[c * 4]       = make_float4(df0[0], df0[1], df0[2], df0[3]);
                *(float4*)&E[16 + c * 4]  = make_float4(dm0[0], dm0[1], dm0[2], dm0[3]);
                *(float4*)&E[32 + c * 4]  = make_float4(sf0[0], sf0[1], sf0[2], sf0[3]);
                *(float4*)&E[48 + c * 4]  = make_float4(sm0[0], sm0[1], sm0[2], sm0[3]);
                *(float4*)&E[64 + c * 4]  = make_float4(df1[0]+dm1[0], df1[1]+dm1[1], df1[2]+dm1[2], df1[3]+dm1[3]);
                *(float4*)&E[80 + c * 4]  = make_float4(sf1[0]+sm1[0], sf1[1]+sm1[1], sf1[2]+sm1[2], sf1[3]+sm1[3]);
                *(float4*)&E[96 + c * 4]  = make_float4(df1[0]-dm1[0], df1[1]-dm1[1], df1[2]-dm1[2], df1[3]-dm1[3]);
                *(float4*)&E[112 + c * 4] = make_float4(sf1[0]-sm1[0], sf1[1]-sm1[1], sf1[2]-sm1[2], sf1[3]-sm1[3]);
#pragma unroll
                for (int j = 0; j < 4; j++) {
                    ped[j]=0.f; pod[j]=0.f; qed[j]=0.f; qod[j]=0.f;
                    pex[j]=0.f; pox[j]=0.f; qex[j]=0.f; qox[j]=0.f;
                }
            } else {
#pragma unroll
                for (int j = 0; j < 4; j++) {
                    float p0d = df0[j] + dm0[j], q0d = df0[j] - dm0[j];
                    float p1d = df1[j] + dm1[j], q1d = df1[j] - dm1[j];
                    ped[j] = p0d + p1d;  pod[j] = p0d - p1d;
                    qed[j] = q0d - q1d;  qod[j] = q0d + q1d;
                    float p0x = sf0[j] + sm0[j], q0x = sf0[j] - sm0[j];
                    float p1x = sf1[j] + sm1[j], q1x = sf1[j] - sm1[j];
                    pex[j] = p0x + p1x;  pox[j] = p0x - p1x;
                    qex[j] = q0x - q1x;  qox[j] = q0x + q1x;
                }
            }
            int soff = (bl * 32 + t) * 16 + c * 4;
            *(float4*)&s_Epd[soff] = make_float4(ped[0], ped[1], ped[2], ped[3]);
            *(float4*)&s_Eqd[soff] = make_float4(qed[0], qed[1], qed[2], qed[3]);
            *(float4*)&s_Epx[soff] = make_float4(pex[0], pex[1], pex[2], pex[3]);
            *(float4*)&s_Eqx[soff] = make_float4(qex[0], qex[1], qex[2], qex[3]);
            *(float4*)&s_Opd[soff] = make_float4(pod[0], pod[1], pod[2], pod[3]);
            *(float4*)&s_Oqd[soff] = make_float4(qod[0], qod[1], qod[2], qod[3]);
            *(float4*)&s_Opx[soff] = make_float4(pox[0], pox[1], pox[2], pox[3]);
            *(float4*)&s_Oqx[soff] = make_float4(qox[0], qox[1], qox[2], qox[3]);
        }
        __syncthreads();
        const float* sp = (f0 < 32) ? (arr ? s_Epx : s_Epd) : (arr ? s_Opx : s_Opd);
        const float* sq = (f0 < 32) ? (arr ? s_Eqx : s_Eqd) : (arr ? s_Oqx : s_Oqd);
#pragma unroll 4
        for (int tt = 0; tt < 32; tt++) {
            int base = (bloc * 32 + tt) * 16;
            ulonglong2 pA = *(const ulonglong2*)&sp[base + i0];
            ulonglong2 pB = *(const ulonglong2*)&sp[base + i0 + 4];
            ulonglong2 qA = *(const ulonglong2*)&sq[base + i0];
            ulonglong2 qB = *(const ulonglong2*)&sq[base + i0 + 4];
            float4 cv = *(const float4*)&s_tc[tt * 64 + f0];
            float4 sv = *(const float4*)&s_ts[tt * 64 + f0];
            u64t cb[4], sb[4];
            PACK2(cb[0], cv.x); PACK2(cb[1], cv.y); PACK2(cb[2], cv.z); PACK2(cb[3], cv.w);
            PACK2(sb[0], sv.x); PACK2(sb[1], sv.y); PACK2(sb[2], sv.z); PACK2(sb[3], sv.w);
            u64t pvv[4] = {pA.x, pA.y, pB.x, pB.y};
            u64t qvv[4] = {qA.x, qA.y, qB.x, qB.y};
#pragma unroll
            for (int iip = 0; iip < 4; iip++)
#pragma unroll
                for (int ff = 0; ff < 4; ff++) {
                    FMA2(aR2[iip][ff], pvv[iip], cb[ff]);
                    FMA2(aI2[iip][ff], qvv[iip], sb[ff]);
                }
        }
        __syncthreads();
    }
    float2* P = (float2*)g_part;
    int b = b0 + bloc;
    size_t base = (((size_t)arr * BB + b) * TOTCH + choff + ch) * 64;
#pragma unroll
    for (int iip = 0; iip < 4; iip++)
#pragma unroll
        for (int ff = 0; ff < 4; ff++) {
            int g = f0 + ff;
            int f = (g < 32) ? (2 * g) : (2 * (g - 32) + 1);
            float r0, r1, q0, q1;
            UNPACK2(r0, r1, aR2[iip][ff]);
            UNPACK2(q0, q1, aI2[iip][ff]);
            P[(base + f) * 16 + i0 + 2 * iip]     = make_float2(r0, -q0);
            P[(base + f) * 16 + i0 + 2 * iip + 1] = make_float2(r1, -q1);
        }
}

// ---------------- merged mix: 256 threads = 8 warps, one f per warp ----------------
__global__ void __launch_bounds__(256) mix_kernel() {
    const int nch[5] = {32, 16, 8, 8, 4};
    const int cho[5] = {0, 32, 48, 56, 64};
    int tid = threadIdx.x;
    int wid = tid >> 5, lane = tid & 31;
    int f = blockIdx.x * 8 + wid;
    int b = blockIdx.y;
    int lev = blockIdx.z;
    int m = 16384 >> (lev + 1);
    __shared__ float Dre[8][16], Dim[8][16], Xre[8][16], Xim[8][16];
    int arr = lane >> 4, i = lane & 15;
    const float2* P = (const float2*)g_part;
    float sre = 0.f, sim = 0.f;
    size_t base = (((size_t)arr * BB + b) * TOTCH + cho[lev]) * 64 + f;
    int nc = nch[lev];
    for (int ch = 0; ch < nc; ch++) {
        float2 p = P[(base + (size_t)ch * 64) * 16 + i];
        sre += p.x; sim += p.y;
    }
    float par  = (f & 1) ? -1.f : 1.f;
    float cpi4 = (f & 1) ? 0.f : ((f & 2) ? -1.f : 1.f);
    float spi4 = (f & 1) ? ((f & 2) ? -1.f : 1.f) : 0.f;
    const float* E = &g_edge[(lev * BB + b) * 128];
    sre += E[(arr ? 32 : 0) + i] + par * E[(arr ? 48 : 16) + i]
         + cpi4 * E[64 + arr * 16 + i];
    sim -= spi4 * E[96 + arr * 16 + i];
    if (arr == 0) { Dre[wid][i] = sre; Dim[wid][i] = sim; }
    else          { Xre[wid][i] = sre; Xim[wid][i] = sim; }
    __syncwarp();
    float r = 0.f, q = 0.f;
    if (arr == 0) {
#pragma unroll
        for (int ii = 0; ii < 16; ii++) {
            float ar = g_wT[0 * 16384 + f * 256 + ii * 16 + i];
            float ai = g_wT[1 * 16384 + f * 256 + ii * 16 + i];
            r += Dre[wid][ii] * ar - Dim[wid][ii] * ai;
            q += Dre[wid][ii] * ai + Dim[wid][ii] * ar;
            float br = g_wT[2 * 16384 + f * 256 + ii * 16 + i];
            float bi = g_wT[3 * 16384 + f * 256 + ii * 16 + i];
            r += Xre[wid][ii] * br - Xim[wid][ii] * bi;
            q += Xre[wid][ii] * bi + Xim[wid][ii] * br;
        }
    } else {
#pragma unroll
        for (int ii = 0; ii < 16; ii++) {
            float cr = g_wT[4 * 16384 + f * 256 + ii * 16 + i];
            float ci = g_wT[5 * 16384 + f * 256 + ii * 16 + i];
            r += Dre[wid][ii] * cr - Dim[wid][ii] * ci;
            q += Dre[wid][ii] * ci + Dim[wid][ii] * cr;
        }
    }
    float wf = (f == 0) ? (1.0f / (float)m) : (2.0f / (float)m);
    size_t o = (size_t)lev * BB * 4096 + (((size_t)b * 2 + arr) * 128 + 2 * f) * 16 + i;
    g_spec[o]      = r * wf;
    g_spec[o + 16] = -q * wf;
}

// ---------------- edge rows y[m/4], y[3m/4] for levels 0..4 ----------------
__global__ void edge4_kernel(float* __restrict__ pUd, float* __restrict__ pUs) {
    const int ms[5]   = {8192, 4096, 2048, 1024, 512};
    const int offs[5] = {0, 8192, 12288, 14336, 15360};
    int lev = blockIdx.x, b = blockIdx.y;
    int tid = threadIdx.x;
    int arr = tid >> 4, j = tid & 15;
    int m = ms[lev];
    const float* sp = g_spec + (size_t)lev * BB * 4096 + ((size_t)b * 2 + arr) * 2048;
    float a1 = 0.f, a2 = 0.f;
#pragma unroll
    for (int f = 0; f < 64; f++) {
        float rw = sp[32 * f + j], qw = sp[32 * f + 16 + j];
        int fm = f & 3;
        if (fm == 0)      { a1 += rw; a2 += rw; }
        else if (fm == 1) { a1 += qw; a2 -= qw; }
        else if (fm == 2) { a1 -= rw; a2 -= rw; }
        else              { a1 -= qw; a2 += qw; }
    }
    float* out = (arr ? pUs : pUd) + (size_t)BB * CKD * offs[lev];
    out[((size_t)b * m + m / 4) * 16 + j]     = a1;
    out[((size_t)b * m + 3 * (m / 4)) * 16 + j] = a2;
}

// =================================================================
// inv4: inverse truncated DFT with QUARTER symmetry, f32x2-packed.
// =================================================================
__global__ void __launch_bounds__(256, 2) inv4_kernel(float* __restrict__ pUd,
                                                      float* __restrict__ pUs, int bxoff) {
    const int tstart[5] = {0, 64, 96, 112, 120};
    const int offs[5]   = {0, 8192, 12288, 14336, 15360};
    extern __shared__ float sm[];
    float* sB = sm;
    float* sA = sB + 16384;
    int tid = threadIdx.x;
    int bx = blockIdx.x + bxoff;
    int lev;
    if (bx < 64) lev = 0; else if (bx < 96) lev = 1; else if (bx < 112) lev = 2;
    else if (bx < 120) lev = 3; else lev = 4;
    int m = 16384 >> (lev + 1);
    int stride = 1 << lev;
    int t0 = (bx - tstart[lev]) * 32;
    int b0 = blockIdx.y * 4;
    float* outUd = pUd + (size_t)BB * CKD * offs[lev];
    float* outUs = pUs + (size_t)BB * CKD * offs[lev];

    const float4* spec4 = (const float4*)g_spec + (size_t)lev * BB * 1024;
    float4* sB4 = (float4*)sB;
    for (int id = tid; id < 4096; id += 256) {
        int k = id >> 5, col4 = id & 31;
        int f = k >> 1, isq = k & 1;
        int g = (f & 1) ? (32 + (f >> 1)) : (f >> 1);
        int bl = col4 >> 3, arr = (col4 >> 2) & 1, j4 = col4 & 3;
        sB4[(2 * g + isq) * 32 + col4] = spec4[(((size_t)(b0 + bl) * 2 + arr) * 128 + k) * 4 + j4];
    }
    const float2* TP = (const float2*)g_tabTP;
    int tl = tid & 31;
    int gq = tid >> 5;
    auto stageA = [&](int st, int buf) {
#pragma unroll
        for (int q = 0; q < 2; q++) {
            int gp = gq * 2 + q;
            int g = st * 16 + gp;
            float2 cs = TP[(size_t)g * 2048 + (size_t)(t0 + tl) * stride];
            sA[buf * 1024 + (2 * gp) * 32 + tl]     = cs.x;
            sA[buf * 1024 + (2 * gp + 1) * 32 + tl] = cs.y;
        }
    };
    stageA(0, 0);
    __syncthreads();

    int cg = tid & 31;
    int tg = tid >> 5;
    u64t uE[4][2] = {}, uO[4][2] = {}, vE[4][2] = {}, vO[4][2] = {};

#pragma unroll
    for (int st = 0; st < 4; st++) {
        if (st < 3) stageA(st + 1, (st & 1) ^ 1);
        const float* A = &sA[(st & 1) * 1024];
        const float* Bst = &sB[st * 32 * 128];
#pragma unroll 4
        for (int gp = 0; gp < 16; gp++) {
            float4 ac = *(const float4*)&A[(2 * gp) * 32 + tg * 4];
            float4 as = *(const float4*)&A[(2 * gp + 1) * 32 + tg * 4];
            ulonglong2 bu = *(const ulonglong2*)&Bst[(2 * gp) * 128 + cg * 4];
            ulonglong2 bv = *(const ulonglong2*)&Bst[(2 * gp + 1) * 128 + cg * 4];
            float acv[4] = {ac.x, ac.y, ac.z, ac.w};
            float asv[4] = {as.x, as.y, as.z, as.w};
#pragma unroll
            for (int r = 0; r < 4; r++) {
                u64t ab, sb;
                PACK2(ab, acv[r]);
                PACK2(sb, asv[r]);
                if (st < 2) {
                    FMA2(uE[r][0], ab, bu.x); FMA2(uE[r][1], ab, bu.y);
                    FMA2(vE[r][0], sb, bv.x); FMA2(vE[r][1], sb, bv.y);
                } else {
                    FMA2(uO[r][0], ab, bu.x); FMA2(uO[r][1], ab, bu.y);
                    FMA2(vO[r][0], sb, bv.x); FMA2(vO[r][1], sb, bv.y);
                }
            }
        }
        __syncthreads();
    }
    int bl = cg >> 3, arr = (cg >> 2) & 1, j0 = (cg & 3) * 4;
    float* outp = (arr ? outUs : outUd) + ((size_t)(b0 + bl) * m) * 16 + j0;
#pragma unroll
    for (int r = 0; r < 4; r++) {
        int t = t0 + tg * 4 + r;
        float ue[4], uo[4], ve[4], vo[4];
#pragma unroll
        for (int cp = 0; cp < 2; cp++) {
            UNPACK2(ue[2*cp], ue[2*cp+1], uE[r][cp]);
            UNPACK2(uo[2*cp], uo[2*cp+1], uO[r][cp]);
            UNPACK2(ve[2*cp], ve[2*cp+1], vE[r][cp]);
            UNPACK2(vo[2*cp], vo[2*cp+1], vO[r][cp]);
        }
        float y0[4], y1[4], y2[4], y3[4];
#pragma unroll
        for (int c = 0; c < 4; c++) {
            float su = ue[c] + uo[c], du = ue[c] - uo[c];
            float sv = ve[c] + vo[c], dv = ve[c] - vo[c];
            y0[c] = su + sv;
            y1[c] = su - sv;
            y2[c] = du - dv;
            y3[c] = du + dv;
        }
        *(float4*)&outp[(size_t)t * 16] = make_float4(y0[0], y0[1], y0[2], y0[3]);
        if (t > 0) {
            *(float4*)&outp[(size_t)(m - t) * 16]     = make_float4(y1[0], y1[1], y1[2], y1[3]);
            *(float4*)&outp[(size_t)(m / 2 - t) * 16] = make_float4(y2[0], y2[1], y2[2], y2[3]);
            *(float4*)&outp[(size_t)(m / 2 + t) * 16] = make_float4(y3[0], y3[1], y3[2], y3[3]);
        } else {
            *(float4*)&outp[(size_t)(m / 2) * 16]     = make_float4(y2[0], y2[1], y2[2], y2[3]);
        }
    }
}

// =================================================================
// deep_kernel: levels 5..13 (m=256..1) entirely in smem.
// Input: 512 rows/batch (dfwd4 output). Output: 512 rows/batch.
// =================================================================
__global__ void __launch_bounds__(256, 1) deep_kernel(
        const float* __restrict__ xin, float* __restrict__ xout,
        const float* __restrict__ ecd, const float* __restrict__ ecs,
        const float* __restrict__ rce, const float* __restrict__ rco,
        const float* __restrict__ t0w, const float* __restrict__ t0b) {
    extern __shared__ float dsm[];
    float* X0 = dsm;             // 8192
    float* X1 = X0 + 8192;       // 8192
    float* D  = X1 + 8192;       // 4096
    float* UD = D + 4096;        // 8176 (511 rows)
    float* US = UD + 8176;       // 8176
    float* SP = US + 8176;       // 4096
    float* MS = SP + 4096;       // 4096
    __shared__ float fl[148];
    int b = blockIdx.x, tid = threadIdx.x;
    if (tid < 32)       fl[tid] = ecd[tid];
    else if (tid < 64)  fl[tid] = ecs[tid - 32];
    else if (tid < 96)  fl[tid] = rce[tid - 64];
    else if (tid < 128) fl[tid] = rco[tid - 96];
    else if (tid < 144) fl[tid] = t0w[tid - 128];
    else if (tid < 148) fl[tid] = t0b[tid - 144];
    for (int i = tid; i < 8192; i += 256) X0[i] = xin[(size_t)b * 8192 + i];
    __syncthreads();

    float* xc = X0; float* xn = X1;
    int loff[9];
    int off = 0;
    for (int li = 0; li < 9; li++) { loff[li] = off; off += 256 >> li; }

    for (int li = 0; li < 9; li++) {
        int m = 256 >> li;
        int stride = 8192 / m;
        for (int it = tid; it < m * 4; it += 256) {
            int c = it & 3, s = it >> 2;
            float xa[8];
#pragma unroll
            for (int p = 0; p < 4; p++) {
                xa[p]     = xc[(2 * s) * 16 + c * 4 + p];
                xa[p + 4] = xc[(2 * s + 1) * 16 + c * 4 + p];
            }
            float dv[4] = {0, 0, 0, 0}, sv[4] = {0, 0, 0, 0};
#pragma unroll
            for (int p = 0; p < 8; p++) {
                float xv = xa[p];
#pragma unroll
                for (int j = 0; j < 4; j++) {
                    dv[j] += xv * fl[p * 4 + j];
                    sv[j] += xv * fl[32 + p * 4 + j];
                }
            }
#pragma unroll
            for (int j = 0; j < 4; j++) {
                D[s * 16 + c * 4 + j]  = dv[j];
                xn[s * 16 + c * 4 + j] = sv[j];
            }
        }
        __syncthreads();
        int l = (m / 2 + 1 < 64) ? m / 2 + 1 : 64;
        for (int it = tid; it < 2 * l * 16; it += 256) {
            int i = it & 15;
            int f = (it >> 4) % l;
            int arr = it / (16 * l);
            const float* src = arr ? xn : D;
            float re = 0.f, im = 0.f;
            for (int t = 0; t < m; t++) {
                float v = src[t * 16 + i];
                re += v * g_tabc[(t * stride) * 64 + f];
                im -= v * g_tabs[(t * stride) * 64 + f];
            }
            SP[((arr * 64 + f) * 2 + 0) * 16 + i] = re;
            SP[((arr * 64 + f) * 2 + 1) * 16 + i] = im;
        }
        __syncthreads();
        for (int it = tid; it < 2 * l * 16; it += 256) {
            int o = it & 15;
            int f = (it >> 4) % l;
            int arr = it / (16 * l);
            float r = 0.f, q = 0.f;
            if (arr == 0) {
#pragma unroll 4
                for (int i2 = 0; i2 < 16; i2++) {
                    float Dr = SP[((0 * 64 + f) * 2 + 0) * 16 + i2];
                    float Di = SP[((0 * 64 + f) * 2 + 1) * 16 + i2];
                    float Xr = SP[((1 * 64 + f) * 2 + 0) * 16 + i2];
                    float Xi = SP[((1 * 64 + f) * 2 + 1) * 16 + i2];
                    float ar = g_wT[0 * 16384 + f * 256 + i2 * 16 + o];
                    float ai = g_wT[1 * 16384 + f * 256 + i2 * 16 + o];
                    float br = g_wT[2 * 16384 + f * 256 + i2 * 16 + o];
                    float bi = g_wT[3 * 16384 + f * 256 + i2 * 16 + o];
                    r += Dr * ar - Di * ai + Xr * br - Xi * bi;
                    q += Dr * ai + Di * ar + Xr * bi + Xi * br;
                }
            } else {
#pragma unroll 4
                for (int i2 = 0; i2 < 16; i2++) {
                    float Dr = SP[((0 * 64 + f) * 2 + 0) * 16 + i2];
                    float Di = SP[((0 * 64 + f) * 2 + 1) * 16 + i2];
                    float cr = g_wT[4 * 16384 + f * 256 + i2 * 16 + o];
                    float ci = g_wT[5 * 16384 + f * 256 + i2 * 16 + o];
                    r += Dr * cr - Di * ci;
                    q += Dr * ci + Di * cr;
                }
            }
            float wf = (f == 0 || 2 * f == m) ? (1.0f / (float)m) : (2.0f / (float)m);
            MS[((arr * 64 + f) * 2 + 0) * 16 + o] = r * wf;
            MS[((arr * 64 + f) * 2 + 1) * 16 + o] = q * wf;
        }
        __syncthreads();
        for (int it = tid; it < 2 * m * 16; it += 256) {
            int o = it & 15;
            int t = (it >> 4) % m;
            int arr = it / (16 * m);
            float acc = 0.f;
            for (int f = 0; f < l; f++) {
                float r = MS[((arr * 64 + f) * 2 + 0) * 16 + o];
                float q = MS[((arr * 64 + f) * 2 + 1) * 16 + o];
                acc += r * g_tabc[(t * stride) * 64 + f] - q * g_tabs[(t * stride) * 64 + f];
            }
            (arr ? US : UD)[(loff[li] + t) * 16 + o] = acc;
        }
        __syncthreads();
        float* tmp = xc; xc = xn; xn = tmp;
    }
    if (tid < 16) {
        int c = tid >> 2, o = tid & 3;
        float acc = fl[144 + o];
#pragma unroll
        for (int p = 0; p < 4; p++) acc += xc[c * 4 + p] * fl[128 + o * 4 + p];
        xn[tid] = acc;
    }
    __syncthreads();
    { float* tmp = xc; xc = xn; xn = tmp; }
    for (int li = 8; li >= 0; li--) {
        int m = 256 >> li;
        for (int it = tid; it < m * 4; it += 256) {
            int c = it & 3, s = it >> 2;
            float xs[4], ud[4];
#pragma unroll
            for (int j = 0; j < 4; j++) {
                xs[j] = xc[s * 16 + c * 4 + j] + US[(loff[li] + s) * 16 + c * 4 + j];
                ud[j] = UD[(loff[li] + s) * 16 + c * 4 + j];
            }
            float e[4] = {0, 0, 0, 0}, o4[4] = {0, 0, 0, 0};
#pragma unroll
            for (int p = 0; p < 4; p++)
#pragma unroll
                for (int j = 0; j < 4; j++) {
                    e[j]  += xs[p] * fl[64 + p * 4 + j] + ud[p] * fl[64 + (p + 4) * 4 + j];
                    o4[j] += xs[p] * fl[96 + p * 4 + j] + ud[p] * fl[96 + (p + 4) * 4 + j];
                }
#pragma unroll
            for (int j = 0; j < 4; j++) {
                xn[(2 * s) * 16 + c * 4 + j]     = e[j];
                xn[(2 * s + 1) * 16 + c * 4 + j] = o4[j];
            }
        }
        __syncthreads();
        float* tmp = xc; xc = xn; xn = tmp;
    }
    for (int i = tid; i < 8192; i += 256) xout[(size_t)b * 8192 + i] = xc[i];
}

// ---------------- reconstruction step (levels 0-4) ----------------
__global__ void recon_kernel(const float* __restrict__ xin, const float* __restrict__ Ud,
                             const float* __restrict__ Us, const float* __restrict__ rce,
                             const float* __restrict__ rco, float* __restrict__ out, int m) {
    __shared__ float se[32], so[32];
    int tid = threadIdx.x;
    if (tid < 32)      se[tid]      = rce[tid];
    else if (tid < 64) so[tid - 32] = rco[tid - 32];
    __syncthreads();
    int idx = blockIdx.x * blockDim.x + tid;
    if (idx >= BB * m * 4) return;
    int c = idx & 3;
    int s = (idx >> 2) % m;
    int b = idx / (m * 4);
    size_t r = ((size_t)b * m + s) * 16 + c * 4;
    float4 xv = *(const float4*)&xin[r];
    float4 uv = *(const float4*)&Us[r];
    float4 dv = *(const float4*)&Ud[r];
    float xs[4] = {xv.x + uv.x, xv.y + uv.y, xv.z + uv.z, xv.w + uv.w};
    float ud[4] = {dv.x, dv.y, dv.z, dv.w};
    float e[4] = {0, 0, 0, 0}, o[4] = {0, 0, 0, 0};
#pragma unroll
    for (int p = 0; p < 4; p++)
#pragma unroll
        for (int j = 0; j < 4; j++) {
            e[j] += xs[p] * se[p * 4 + j] + ud[p] * se[(p + 4) * 4 + j];
            o[j] += xs[p] * so[p * 4 + j] + ud[p] * so[(p + 4) * 4 + j];
        }
    size_t w = ((size_t)b * 2 * m + 2 * s) * 16 + c * 4;
    *(float4*)&out[w]      = make_float4(e[0], e[1], e[2], e[3]);
    *(float4*)&out[w + 16] = make_float4(o[0], o[1], o[2], o[3]);
}

// ---------------- side streams + events (host objects, created once) ----------------
struct SideStreams {
    cudaStream_t sB = nullptr, sC = nullptr;
    cudaEvent_t evRoot = nullptr, evB = nullptr, evD = nullptr, evC = nullptr,
                evMix = nullptr, evI1 = nullptr, evR = nullptr;
    void ensure() {
        if (sB) return;
        cudaStreamCreateWithFlags(&sB, cudaStreamNonBlocking);
        cudaStreamCreateWithFlags(&sC, cudaStreamNonBlocking);
        cudaEventCreateWithFlags(&evRoot, cudaEventDisableTiming);
        cudaEventCreateWithFlags(&evB,    cudaEventDisableTiming);
        cudaEventCreateWithFlags(&evD,    cudaEventDisableTiming);
        cudaEventCreateWithFlags(&evC,    cudaEventDisableTiming);
        cudaEventCreateWithFlags(&evMix,  cudaEventDisableTiming);
        cudaEventCreateWithFlags(&evI1,   cudaEventDisableTiming);
        cudaEventCreateWithFlags(&evR,    cudaEventDisableTiming);
    }
};
static SideStreams g_ss;

// ---------------- host orchestration ----------------
extern "C" void kernel_launch(void* const* d_in, const int* in_sizes, int n_in,
                              void* d_out, int out_size) {
    const float* x_in = (const float*)d_in[0];
    const float* ec_s = (const float*)d_in[1];
    const float* ec_d = (const float*)d_in[2];
    const float* rc_e = (const float*)d_in[3];
    const float* rc_o = (const float*)d_in[4];
    const float* t0_w = (const float*)d_in[5];
    const float* t0_b = (const float*)d_in[6];

    g_ss.ensure();

    const int DFWD_SM = 20480 * 4;
    const int INV_SM  = (16384 + 2048) * 4;
    const int DEEP_SM = (8192 + 8192 + 4096 + 8176 + 8176 + 4096 + 4096) * 4;  // 180096
    cudaFuncSetAttribute(dfwd_kernel, cudaFuncAttributeMaxDynamicSharedMemorySize, DFWD_SM);
    cudaFuncSetAttribute(inv4_kernel, cudaFuncAttributeMaxDynamicSharedMemorySize, INV_SM);
    cudaFuncSetAttribute(deep_kernel, cudaFuncAttributeMaxDynamicSharedMemorySize, DEEP_SM);

    float *px0, *px1, *pd, *pUd, *pUs;
    cudaGetSymbolAddress((void**)&px0, g_x0);
    cudaGetSymbolAddress((void**)&px1, g_x1);
    cudaGetSymbolAddress((void**)&pd,  g_d);
    cudaGetSymbolAddress((void**)&pUd, g_Ud);
    cudaGetSymbolAddress((void**)&pUs, g_Us);

    // ---- fork stream B at root: full tab_row (deep only) + tab_T... + wprep ----
    cudaEventRecord(g_ss.evRoot, 0);
    cudaStreamWaitEvent(g_ss.sB, g_ss.evRoot, 0);
    tab_row_kernel<<<2048, 256, 0, g_ss.sB>>>();
    wprep_kernel<<<(6 * 16384 + 255) / 256, 256, 0, g_ss.sB>>>(
        (const float*)d_in[7], (const float*)d_in[8], (const float*)d_in[9],
        (const float*)d_in[10], (const float*)d_in[11], (const float*)d_in[12]);
    cudaEventRecord(g_ss.evB, g_ss.sB);

    // ---- main stream: quarter twiddle tables, then dfwd chain (levels 0..4) ----
    tab_rowP_kernel<<<512, 256>>>();

    float* xb[2] = {px0, px1};
    const int nchunks[5] = {32, 16, 8, 8, 4};
    const int choffs[5]  = {0, 32, 48, 56, 64};
    size_t offs[5];
    size_t off = 0;
    const float* src = x_in;

    for (int lev = 0; lev < 5; lev++) {
        int m = NN >> (lev + 1);                 // 8192..512
        offs[lev] = off;
        int stride = MAXM / m;
        float* xnext = xb[lev & 1];
        dfwd_kernel<<<dim3(8, nchunks[lev]), 256, DFWD_SM>>>(
            src, xnext, ec_d, ec_s, m, stride, nchunks[lev], choffs[lev], lev);
        off += m;
        src = xnext;
    }

    // ---- fork stream C: deep_kernel (levels 5..13, input 512 rows/batch) ----
    cudaEventRecord(g_ss.evD, 0);
    cudaStreamWaitEvent(g_ss.sC, g_ss.evD, 0);
    cudaStreamWaitEvent(g_ss.sC, g_ss.evB, 0);
    deep_kernel<<<BB, 256, DEEP_SM, g_ss.sC>>>(src, pd, ec_d, ec_s, rc_e, rc_o, t0_w, t0_b);
    cudaEventRecord(g_ss.evC, g_ss.sC);

    // ---- main: mix, edge4 on B, inv4 levels 1-4 ----
    cudaStreamWaitEvent(0, g_ss.evB, 0);
    mix_kernel<<<dim3(8, BB, 5), 256>>>();
    cudaEventRecord(g_ss.evMix, 0);
    cudaStreamWaitEvent(g_ss.sB, g_ss.evMix, 0);
    edge4_kernel<<<dim3(5, BB), 32, 0, g_ss.sB>>>(pUd, pUs);

    inv4_kernel<<<dim3(60, 8), 256, INV_SM>>>(pUd, pUs, 64);   // levels 1..4
    cudaEventRecord(g_ss.evI1, 0);

    // ---- recon levels 4..1 on stream B, concurrent with inv4 level 0 ----
    cudaStreamWaitEvent(g_ss.sB, g_ss.evI1, 0);
    cudaStreamWaitEvent(g_ss.sB, g_ss.evC, 0);
    const float* curx = pd;
    int flip = 0;
    for (int lev = 4; lev >= 1; lev--) {
        int m = NN >> (lev + 1);
        float* dst = xb[flip];
        int total = BB * m * 4;
        recon_kernel<<<(total + 255) / 256, 256, 0, g_ss.sB>>>(
            curx, pUd + (size_t)BB * CKD * offs[lev], pUs + (size_t)BB * CKD * offs[lev],
            rc_e, rc_o, dst, m);
        curx = dst;
        flip ^= 1;
    }
    cudaEventRecord(g_ss.evR, g_ss.sB);

    // ---- main: inv4 level 0 (64 tiles), then final recon ----
    inv4_kernel<<<dim3(64, 8), 256, INV_SM>>>(pUd, pUs, 0);
    cudaStreamWaitEvent(0, g_ss.evR, 0);
    {
        int m = NN >> 1;
        int total = BB * m * 4;
        recon_kernel<<<(total + 255) / 256, 256>>>(
            curx, pUd + (size_t)BB * CKD * offs[0], pUs + (size_t)BB * CKD * offs[0],
            rc_e, rc_o, (float*)d_out, m);
    }
}

// round 16
// speedup vs baseline: 1.3635x; 1.3635x over previous
#include <cuda_runtime.h>

#define BB   32
#define NN   16384
#define CKD  16
#define MAXM 8192
#define TOTCH 70

typedef unsigned long long u64t;
#define FMA2(d, a, b)  asm("fma.rn.f32x2 %0, %1, %2, %0;" : "+l"(d) : "l"(a), "l"(b))
#define PACK2(out, x)  asm("mov.b64 %0, {%1, %1};" : "=l"(out) : "f"(x))
#define UNPACK2(lo, hi, in) asm("mov.b64 {%0, %1}, %2;" : "=f"(lo), "=f"(hi) : "l"(in))

// ---------------- device scratch (static, no allocations) ----------------
__device__ __align__(256) float g_x0 [BB*MAXM*CKD];
__device__ __align__(256) float g_x1 [BB*MAXM*CKD];
__device__ __align__(256) float g_d  [BB*MAXM*CKD];
__device__ __align__(256) float g_Ud [BB*(NN-1)*CKD];
__device__ __align__(256) float g_Us [BB*(NN-1)*CKD];
__device__ __align__(256) float g_part[2ull*BB*TOTCH*64*CKD*2];
__device__ __align__(256) float g_spec[6ull*BB*4096];   // [lev][b][arr][k=2f(re)/2f+1(-im*wf)][j]
__device__ __align__(256) float g_edge[6*BB*128];       // [lev][b][d0|dmh|x0|xmh|pd|px|qd|qx]
__device__ __align__(256) float g_tabc[MAXM*64];        // [t][f] cos (deep kernel, full range)
__device__ __align__(256) float g_tabs[MAXM*64];
__device__ __align__(256) float g_tabcP[2048*64];       // [t][g] parity-permuted cos (t<2048)
__device__ __align__(256) float g_tabsP[2048*64];
__device__ __align__(256) float g_tabTP[64*2048*2];     // [g][t](cos,sin), parity-permuted (t<2048)
__device__ __align__(256) float g_wT  [6*64*16*16];     // [arr][f][i][o]

// ---------------- twiddle tables ----------------
// quarter table (rows t<2048) for dfwd/inv4 — on critical path, small
__global__ void tab_rowP_kernel() {
    int idx = blockIdx.x * blockDim.x + threadIdx.x;   // t*64 + f, t<2048
    int t = idx >> 6, f = idx & 63;
    float ph = (float)(f * t) * (2.0f / 8192.0f);
    float s, c; sincospif(ph, &s, &c);
    int g = (f & 1) ? (32 + (f >> 1)) : (f >> 1);
    g_tabcP[t * 64 + g] = c;
    g_tabsP[t * 64 + g] = s;
    g_tabTP[((size_t)g * 2048 + t) * 2 + 0] = c;
    g_tabTP[((size_t)g * 2048 + t) * 2 + 1] = s;
}
// full table for deep kernel — hidden on stream B
__global__ void tab_row_kernel() {
    int idx = blockIdx.x * blockDim.x + threadIdx.x;   // t*64 + f
    int t = idx >> 6, f = idx & 63;
    float ph = (float)(f * t) * (2.0f / 8192.0f);
    float s, c; sincospif(ph, &s, &c);
    g_tabc[idx] = c;
    g_tabs[idx] = s;
}

// ---------------- weight transpose: [i][o][f] -> [arr][f][i][o] ----------------
__global__ void wprep_kernel(const float* __restrict__ a0, const float* __restrict__ a1,
                             const float* __restrict__ a2, const float* __restrict__ a3,
                             const float* __restrict__ a4, const float* __restrict__ a5) {
    int idx = blockIdx.x * blockDim.x + threadIdx.x;
    if (idx >= 6*16384) return;
    int arr = idx >> 14;
    int r   = idx & 16383;
    int f = r >> 8, i = (r >> 4) & 15, o = r & 15;
    const float* src = (arr == 0) ? a0 : (arr == 1) ? a1 : (arr == 2) ? a2 :
                       (arr == 3) ? a3 : (arr == 4) ? a4 : a5;
    g_wT[idx] = src[(i * 16 + o) * 64 + f];
}

// =================================================================
// dfwd: fused decompose + DOUBLY-FOLDED forward truncated DFT.
// =================================================================
__global__ void __launch_bounds__(256, 2) dfwd_kernel(
        const float* __restrict__ xin, float* __restrict__ xnext,
        const float* __restrict__ ecd, const float* __restrict__ ecs,
        int m, int stride, int nchunk, int choff, int lev) {
    extern __shared__ float sm[];
    float* s_Epd = sm;
    float* s_Eqd = sm + 2048;
    float* s_Epx = sm + 4096;
    float* s_Eqx = sm + 6144;
    float* s_Opd = sm + 8192;
    float* s_Oqd = sm + 10240;
    float* s_Opx = sm + 12288;
    float* s_Oqx = sm + 14336;
    float* s_tc  = sm + 16384;
    float* s_ts  = sm + 18432;
    __shared__ float fl[64];
    int tid = threadIdx.x;
    int b0 = blockIdx.x * 4;
    int ch = blockIdx.y;
    int qm = m >> 2;
    int clen = qm / nchunk;
    int T0base = ch * clen;
    if (tid < 64) fl[tid] = (tid < 32) ? ecd[tid] : ecs[tid - 32];
    __syncthreads();

    int bloc = tid >> 6;
    int sub  = tid & 63;
    int arr  = sub >> 5;
    int lane32 = sub & 31;
    int i0 = (lane32 & 1) * 8;
    int f0 = (lane32 >> 1) * 4;
    u64t aR2[4][4] = {}, aI2[4][4] = {};

    for (int tb = 0; tb < clen; tb += 32) {
        int T0 = T0base + tb;
        {
            float4* tc4 = (float4*)s_tc;
            float4* ts4 = (float4*)s_ts;
            for (int id = tid; id < 512; id += 256) {
                int t = id >> 4, q = id & 15;
                size_t g = ((size_t)(T0 + t) * stride) * 16 + q;
                tc4[id] = ((const float4*)g_tabcP)[g];
                ts4[id] = ((const float4*)g_tabsP)[g];
            }
        }
        for (int id = tid; id < 512; id += 256) {
            int c = id & 3, t = (id >> 2) & 31, bl = id >> 7;
            int s = T0 + t;
            size_t brow = (size_t)(b0 + bl) * (2 * m);
            size_t bnext = (size_t)(b0 + bl) * m;
            int rA0 = s;
            int rB0 = (s == 0) ? (m >> 1) : (m - s);
            int rA1 = (s == 0) ? qm : ((m >> 1) - s);
            int rB1 = (s == 0) ? (3 * qm) : ((m >> 1) + s);
            float df0[4] = {0,0,0,0}, sf0[4] = {0,0,0,0}, dm0[4] = {0,0,0,0}, sm0[4] = {0,0,0,0};
            float df1[4] = {0,0,0,0}, sf1[4] = {0,0,0,0}, dm1[4] = {0,0,0,0}, sm1[4] = {0,0,0,0};
            {
                float4 F0 = *(const float4*)&xin[(brow + 2 * rA0) * 16 + c * 4];
                float4 F1 = *(const float4*)&xin[(brow + 2 * rA0 + 1) * 16 + c * 4];
                float4 M0 = *(const float4*)&xin[(brow + 2 * rB0) * 16 + c * 4];
                float4 M1 = *(const float4*)&xin[(brow + 2 * rB0 + 1) * 16 + c * 4];
                float xf[8] = {F0.x, F0.y, F0.z, F0.w, F1.x, F1.y, F1.z, F1.w};
                float xm[8] = {M0.x, M0.y, M0.z, M0.w, M1.x, M1.y, M1.z, M1.w};
#pragma unroll
                for (int p = 0; p < 8; p++) {
                    float a = xf[p], bv = xm[p];
#pragma unroll
                    for (int j = 0; j < 4; j++) {
                        df0[j] += a * fl[p * 4 + j];
                        sf0[j] += a * fl[32 + p * 4 + j];
                        dm0[j] += bv * fl[p * 4 + j];
                        sm0[j] += bv * fl[32 + p * 4 + j];
                    }
                }
                *(float4*)&xnext[(bnext + rA0) * 16 + c * 4] = make_float4(sf0[0], sf0[1], sf0[2], sf0[3]);
                *(float4*)&xnext[(bnext + rB0) * 16 + c * 4] = make_float4(sm0[0], sm0[1], sm0[2], sm0[3]);
            }
            {
                float4 F0 = *(const float4*)&xin[(brow + 2 * rA1) * 16 + c * 4];
                float4 F1 = *(const float4*)&xin[(brow + 2 * rA1 + 1) * 16 + c * 4];
                float4 M0 = *(const float4*)&xin[(brow + 2 * rB1) * 16 + c * 4];
                float4 M1 = *(const float4*)&xin[(brow + 2 * rB1 + 1) * 16 + c * 4];
                float xf[8] = {F0.x, F0.y, F0.z, F0.w, F1.x, F1.y, F1.z, F1.w};
                float xm[8] = {M0.x, M0.y, M0.z, M0.w, M1.x, M1.y, M1.z, M1.w};
#pragma unroll
                for (int p = 0; p < 8; p++) {
                    float a = xf[p], bv = xm[p];
#pragma unroll
                    for (int j = 0; j < 4; j++) {
                        df1[j] += a * fl[p * 4 + j];
                        sf1[j] += a * fl[32 + p * 4 + j];
                        dm1[j] += bv * fl[p * 4 + j];
                        sm1[j] += bv * fl[32 + p * 4 + j];
                    }
                }
                *(float4*)&xnext[(bnext + rA1) * 16 + c * 4] = make_float4(sf1[0], sf1[1], sf1[2], sf1[3]);
                *(float4*)&xnext[(bnext + rB1) * 16 + c * 4] = make_float4(sm1[0], sm1[1], sm1[2], sm1[3]);
            }
            float ped[4], pod[4], qed[4], qod[4], pex[4], pox[4], qex[4], qox[4];
            if (s == 0) {
                float* E = &g_edge[(lev * BB + (b0 + bl)) * 128];
                *(float4*)&E[c * 4]       = make_float4(df0[0], df0[1], df0[2], df0[3]);
                *(float4*)&E[16 + c * 4]  = make_float4(dm0[0], dm0[1], dm0[2], dm0[3]);
                *(float4*)&E[32 + c * 4]  = make_float4(sf0[0], sf0[1], sf0[2], sf0[3]);
                *(float4*)&E[48 + c * 4]  = make_float4(sm0[0], sm0[1], sm0[2], sm0[3]);
                *(float4*)&E[64 + c * 4]  = make_float4(df1[0]+dm1[0], df1[1]+dm1[1], df1[2]+dm1[2], df1[3]+dm1[3]);
                *(float4*)&E[80 + c * 4]  = make_float4(sf1[0]+sm1[0], sf1[1]+sm1[1], sf1[2]+sm1[2], sf1[3]+sm1[3]);
                *(float4*)&E[96 + c * 4]  = make_float4(df1[0]-dm1[0], df1[1]-dm1[1], df1[2]-dm1[2], df1[3]-dm1[3]);
                *(float4*)&E[112 + c * 4] = make_float4(sf1[0]-sm1[0], sf1[1]-sm1[1], sf1[2]-sm1[2], sf1[3]-sm1[3]);
#pragma unroll
                for (int j = 0; j < 4; j++) {
                    ped[j]=0.f; pod[j]=0.f; qed[j]=0.f; qod[j]=0.f;
                    pex[j]=0.f; pox[j]=0.f; qex[j]=0.f; qox[j]=0.f;
                }
            } else {
#pragma unroll
                for (int j = 0; j < 4; j++) {
                    float p0d = df0[j] + dm0[j], q0d = df0[j] - dm0[j];
                    float p1d = df1[j] + dm1[j], q1d = df1[j] - dm1[j];
                    ped[j] = p0d + p1d;  pod[j] = p0d - p1d;
                    qed[j] = q0d - q1d;  qod[j] = q0d + q1d;
                    float p0x = sf0[j] + sm0[j], q0x = sf0[j] - sm0[j];
                    float p1x = sf1[j] + sm1[j], q1x = sf1[j] - sm1[j];
                    pex[j] = p0x + p1x;  pox[j] = p0x - p1x;
                    qex[j] = q0x - q1x;  qox[j] = q0x + q1x;
                }
            }
            int soff = (bl * 32 + t) * 16 + c * 4;
            *(float4*)&s_Epd[soff] = make_float4(ped[0], ped[1], ped[2], ped[3]);
            *(float4*)&s_Eqd[soff] = make_float4(qed[0], qed[1], qed[2], qed[3]);
            *(float4*)&s_Epx[soff] = make_float4(pex[0], pex[1], pex[2], pex[3]);
            *(float4*)&s_Eqx[soff] = make_float4(qex[0], qex[1], qex[2], qex[3]);
            *(float4*)&s_Opd[soff] = make_float4(pod[0], pod[1], pod[2], pod[3]);
            *(float4*)&s_Oqd[soff] = make_float4(qod[0], qod[1], qod[2], qod[3]);
            *(float4*)&s_Opx[soff] = make_float4(pox[0], pox[1], pox[2], pox[3]);
            *(float4*)&s_Oqx[soff] = make_float4(qox[0], qox[1], qox[2], qox[3]);
        }
        __syncthreads();
        const float* sp = (f0 < 32) ? (arr ? s_Epx : s_Epd) : (arr ? s_Opx : s_Opd);
        const float* sq = (f0 < 32) ? (arr ? s_Eqx : s_Eqd) : (arr ? s_Oqx : s_Oqd);
#pragma unroll 4
        for (int tt = 0; tt < 32; tt++) {
            int base = (bloc * 32 + tt) * 16;
            ulonglong2 pA = *(const ulonglong2*)&sp[base + i0];
            ulonglong2 pB = *(const ulonglong2*)&sp[base + i0 + 4];
            ulonglong2 qA = *(const ulonglong2*)&sq[base + i0];
            ulonglong2 qB = *(const ulonglong2*)&sq[base + i0 + 4];
            float4 cv = *(const float4*)&s_tc[tt * 64 + f0];
            float4 sv = *(const float4*)&s_ts[tt * 64 + f0];
            u64t cb[4], sb[4];
            PACK2(cb[0], cv.x); PACK2(cb[1], cv.y); PACK2(cb[2], cv.z); PACK2(cb[3], cv.w);
            PACK2(sb[0], sv.x); PACK2(sb[1], sv.y); PACK2(sb[2], sv.z); PACK2(sb[3], sv.w);
            u64t pvv[4] = {pA.x, pA.y, pB.x, pB.y};
            u64t qvv[4] = {qA.x, qA.y, qB.x, qB.y};
#pragma unroll
            for (int iip = 0; iip < 4; iip++)
#pragma unroll
                for (int ff = 0; ff < 4; ff++) {
                    FMA2(aR2[iip][ff], pvv[iip], cb[ff]);
                    FMA2(aI2[iip][ff], qvv[iip], sb[ff]);
                }
        }
        __syncthreads();
    }
    float2* P = (float2*)g_part;
    int b = b0 + bloc;
    size_t base = (((size_t)arr * BB + b) * TOTCH + choff + ch) * 64;
#pragma unroll
    for (int iip = 0; iip < 4; iip++)
#pragma unroll
        for (int ff = 0; ff < 4; ff++) {
            int g = f0 + ff;
            int f = (g < 32) ? (2 * g) : (2 * (g - 32) + 1);
            float r0, r1, q0, q1;
            UNPACK2(r0, r1, aR2[iip][ff]);
            UNPACK2(q0, q1, aI2[iip][ff]);
            P[(base + f) * 16 + i0 + 2 * iip]     = make_float2(r0, -q0);
            P[(base + f) * 16 + i0 + 2 * iip + 1] = make_float2(r1, -q1);
        }
}

// ---------------- merged mix: 256 threads = 8 warps, one f per warp ----------------
__global__ void __launch_bounds__(256) mix_kernel() {
    const int nch[6] = {32, 16, 8, 8, 4, 2};
    const int cho[6] = {0, 32, 48, 56, 64, 68};
    int tid = threadIdx.x;
    int wid = tid >> 5, lane = tid & 31;
    int f = blockIdx.x * 8 + wid;
    int b = blockIdx.y;
    int lev = blockIdx.z;
    int m = 16384 >> (lev + 1);
    __shared__ float Dre[8][16], Dim[8][16], Xre[8][16], Xim[8][16];
    int arr = lane >> 4, i = lane & 15;
    const float2* P = (const float2*)g_part;
    float sre = 0.f, sim = 0.f;
    size_t base = (((size_t)arr * BB + b) * TOTCH + cho[lev]) * 64 + f;
    int nc = nch[lev];
    for (int ch = 0; ch < nc; ch++) {
        float2 p = P[(base + (size_t)ch * 64) * 16 + i];
        sre += p.x; sim += p.y;
    }
    float par  = (f & 1) ? -1.f : 1.f;
    float cpi4 = (f & 1) ? 0.f : ((f & 2) ? -1.f : 1.f);
    float spi4 = (f & 1) ? ((f & 2) ? -1.f : 1.f) : 0.f;
    const float* E = &g_edge[(lev * BB + b) * 128];
    sre += E[(arr ? 32 : 0) + i] + par * E[(arr ? 48 : 16) + i]
         + cpi4 * E[64 + arr * 16 + i];
    sim -= spi4 * E[96 + arr * 16 + i];
    if (arr == 0) { Dre[wid][i] = sre; Dim[wid][i] = sim; }
    else          { Xre[wid][i] = sre; Xim[wid][i] = sim; }
    __syncwarp();
    float r = 0.f, q = 0.f;
    if (arr == 0) {
#pragma unroll
        for (int ii = 0; ii < 16; ii++) {
            float ar = g_wT[0 * 16384 + f * 256 + ii * 16 + i];
            float ai = g_wT[1 * 16384 + f * 256 + ii * 16 + i];
            r += Dre[wid][ii] * ar - Dim[wid][ii] * ai;
            q += Dre[wid][ii] * ai + Dim[wid][ii] * ar;
            float br = g_wT[2 * 16384 + f * 256 + ii * 16 + i];
            float bi = g_wT[3 * 16384 + f * 256 + ii * 16 + i];
            r += Xre[wid][ii] * br - Xim[wid][ii] * bi;
            q += Xre[wid][ii] * bi + Xim[wid][ii] * br;
        }
    } else {
#pragma unroll
        for (int ii = 0; ii < 16; ii++) {
            float cr = g_wT[4 * 16384 + f * 256 + ii * 16 + i];
            float ci = g_wT[5 * 16384 + f * 256 + ii * 16 + i];
            r += Dre[wid][ii] * cr - Dim[wid][ii] * ci;
            q += Dre[wid][ii] * ci + Dim[wid][ii] * cr;
        }
    }
    float wf = (f == 0) ? (1.0f / (float)m) : (2.0f / (float)m);
    size_t o = (size_t)lev * BB * 4096 + (((size_t)b * 2 + arr) * 128 + 2 * f) * 16 + i;
    g_spec[o]      = r * wf;
    g_spec[o + 16] = -q * wf;
}

// ---------------- edge rows y[m/4], y[3m/4] for all 6 shallow levels ----------------
__global__ void edge4_kernel(float* __restrict__ pUd, float* __restrict__ pUs) {
    const int ms[6]   = {8192, 4096, 2048, 1024, 512, 256};
    const int offs[6] = {0, 8192, 12288, 14336, 15360, 15872};
    int lev = blockIdx.x, b = blockIdx.y;
    int tid = threadIdx.x;
    int arr = tid >> 4, j = tid & 15;
    int m = ms[lev];
    const float* sp = g_spec + (size_t)lev * BB * 4096 + ((size_t)b * 2 + arr) * 2048;
    float a1 = 0.f, a2 = 0.f;
#pragma unroll
    for (int f = 0; f < 64; f++) {
        float rw = sp[32 * f + j], qw = sp[32 * f + 16 + j];
        int fm = f & 3;
        if (fm == 0)      { a1 += rw; a2 += rw; }
        else if (fm == 1) { a1 += qw; a2 -= qw; }
        else if (fm == 2) { a1 -= rw; a2 -= rw; }
        else              { a1 -= qw; a2 += qw; }
    }
    float* out = (arr ? pUs : pUd) + (size_t)BB * CKD * offs[lev];
    out[((size_t)b * m + m / 4) * 16 + j]     = a1;
    out[((size_t)b * m + 3 * (m / 4)) * 16 + j] = a2;
}

// =================================================================
// inv4: inverse truncated DFT with QUARTER symmetry, f32x2-packed.
// =================================================================
__global__ void __launch_bounds__(256, 2) inv4_kernel(float* __restrict__ pUd,
                                                      float* __restrict__ pUs, int bxoff) {
    const int tstart[6] = {0, 64, 96, 112, 120, 124};
    const int offs[6]   = {0, 8192, 12288, 14336, 15360, 15872};
    extern __shared__ float sm[];
    float* sB = sm;
    float* sA = sB + 16384;
    int tid = threadIdx.x;
    int bx = blockIdx.x + bxoff;
    int lev;
    if (bx < 64) lev = 0; else if (bx < 96) lev = 1; else if (bx < 112) lev = 2;
    else if (bx < 120) lev = 3; else if (bx < 124) lev = 4; else lev = 5;
    int m = 16384 >> (lev + 1);
    int stride = 1 << lev;
    int t0 = (bx - tstart[lev]) * 32;
    int b0 = blockIdx.y * 4;
    float* outUd = pUd + (size_t)BB * CKD * offs[lev];
    float* outUs = pUs + (size_t)BB * CKD * offs[lev];

    const float4* spec4 = (const float4*)g_spec + (size_t)lev * BB * 1024;
    float4* sB4 = (float4*)sB;
    for (int id = tid; id < 4096; id += 256) {
        int k = id >> 5, col4 = id & 31;
        int f = k >> 1, isq = k & 1;
        int g = (f & 1) ? (32 + (f >> 1)) : (f >> 1);
        int bl = col4 >> 3, arr = (col4 >> 2) & 1, j4 = col4 & 3;
        sB4[(2 * g + isq) * 32 + col4] = spec4[(((size_t)(b0 + bl) * 2 + arr) * 128 + k) * 4 + j4];
    }
    const float2* TP = (const float2*)g_tabTP;
    int tl = tid & 31;
    int gq = tid >> 5;
    auto stageA = [&](int st, int buf) {
#pragma unroll
        for (int q = 0; q < 2; q++) {
            int gp = gq * 2 + q;
            int g = st * 16 + gp;
            float2 cs = TP[(size_t)g * 2048 + (size_t)(t0 + tl) * stride];
            sA[buf * 1024 + (2 * gp) * 32 + tl]     = cs.x;
            sA[buf * 1024 + (2 * gp + 1) * 32 + tl] = cs.y;
        }
    };
    stageA(0, 0);
    __syncthreads();

    int cg = tid & 31;
    int tg = tid >> 5;
    u64t uE[4][2] = {}, uO[4][2] = {}, vE[4][2] = {}, vO[4][2] = {};

#pragma unroll
    for (int st = 0; st < 4; st++) {
        if (st < 3) stageA(st + 1, (st & 1) ^ 1);
        const float* A = &sA[(st & 1) * 1024];
        const float* Bst = &sB[st * 32 * 128];
#pragma unroll 4
        for (int gp = 0; gp < 16; gp++) {
            float4 ac = *(const float4*)&A[(2 * gp) * 32 + tg * 4];
            float4 as = *(const float4*)&A[(2 * gp + 1) * 32 + tg * 4];
            ulonglong2 bu = *(const ulonglong2*)&Bst[(2 * gp) * 128 + cg * 4];
            ulonglong2 bv = *(const ulonglong2*)&Bst[(2 * gp + 1) * 128 + cg * 4];
            float acv[4] = {ac.x, ac.y, ac.z, ac.w};
            float asv[4] = {as.x, as.y, as.z, as.w};
#pragma unroll
            for (int r = 0; r < 4; r++) {
                u64t ab, sb;
                PACK2(ab, acv[r]);
                PACK2(sb, asv[r]);
                if (st < 2) {
                    FMA2(uE[r][0], ab, bu.x); FMA2(uE[r][1], ab, bu.y);
                    FMA2(vE[r][0], sb, bv.x); FMA2(vE[r][1], sb, bv.y);
                } else {
                    FMA2(uO[r][0], ab, bu.x); FMA2(uO[r][1], ab, bu.y);
                    FMA2(vO[r][0], sb, bv.x); FMA2(vO[r][1], sb, bv.y);
                }
            }
        }
        __syncthreads();
    }
    int bl = cg >> 3, arr = (cg >> 2) & 1, j0 = (cg & 3) * 4;
    float* outp = (arr ? outUs : outUd) + ((size_t)(b0 + bl) * m) * 16 + j0;
#pragma unroll
    for (int r = 0; r < 4; r++) {
        int t = t0 + tg * 4 + r;
        float ue[4], uo[4], ve[4], vo[4];
#pragma unroll
        for (int cp = 0; cp < 2; cp++) {
            UNPACK2(ue[2*cp], ue[2*cp+1], uE[r][cp]);
            UNPACK2(uo[2*cp], uo[2*cp+1], uO[r][cp]);
            UNPACK2(ve[2*cp], ve[2*cp+1], vE[r][cp]);
            UNPACK2(vo[2*cp], vo[2*cp+1], vO[r][cp]);
        }
        float y0[4], y1[4], y2[4], y3[4];
#pragma unroll
        for (int c = 0; c < 4; c++) {
            float su = ue[c] + uo[c], du = ue[c] - uo[c];
            float sv = ve[c] + vo[c], dv = ve[c] - vo[c];
            y0[c] = su + sv;
            y1[c] = su - sv;
            y2[c] = du - dv;
            y3[c] = du + dv;
        }
        *(float4*)&outp[(size_t)t * 16] = make_float4(y0[0], y0[1], y0[2], y0[3]);
        if (t > 0) {
            *(float4*)&outp[(size_t)(m - t) * 16]     = make_float4(y1[0], y1[1], y1[2], y1[3]);
            *(float4*)&outp[(size_t)(m / 2 - t) * 16] = make_float4(y2[0], y2[1], y2[2], y2[3]);
            *(float4*)&outp[(size_t)(m / 2 + t) * 16] = make_float4(y3[0], y3[1], y3[2], y3[3]);
        } else {
            *(float4*)&outp[(size_t)(m / 2) * 16]     = make_float4(y2[0], y2[1], y2[2], y2[3]);
        }
    }
}

// =================================================================
// deep_kernel: levels 6..13 (m=128..1) entirely in smem.
// =================================================================
__global__ void __launch_bounds__(256, 1) deep_kernel(
        const float* __restrict__ xin, float* __restrict__ xout,
        const float* __restrict__ ecd, const float* __restrict__ ecs,
        const float* __restrict__ rce, const float* __restrict__ rco,
        const float* __restrict__ t0w, const float* __restrict__ t0b) {
    extern __shared__ float dsm[];
    float* X0 = dsm;
    float* X1 = X0 + 4096;
    float* D  = X1 + 4096;
    float* UD = D + 2048;
    float* US = UD + 4080;
    float* SP = US + 4080;
    float* MS = SP + 4096;
    __shared__ float fl[148];
    int b = blockIdx.x, tid = threadIdx.x;
    if (tid < 32)       fl[tid] = ecd[tid];
    else if (tid < 64)  fl[tid] = ecs[tid - 32];
    else if (tid < 96)  fl[tid] = rce[tid - 64];
    else if (tid < 128) fl[tid] = rco[tid - 96];
    else if (tid < 144) fl[tid] = t0w[tid - 128];
    else if (tid < 148) fl[tid] = t0b[tid - 144];
    for (int i = tid; i < 4096; i += 256) X0[i] = xin[(size_t)b * 4096 + i];
    __syncthreads();

    float* xc = X0; float* xn = X1;
    int loff[8];
    int off = 0;
    for (int li = 0; li < 8; li++) { loff[li] = off; off += 128 >> li; }

    for (int li = 0; li < 8; li++) {
        int m = 128 >> li;
        int stride = 8192 / m;
        for (int it = tid; it < m * 4; it += 256) {
            int c = it & 3, s = it >> 2;
            float xa[8];
#pragma unroll
            for (int p = 0; p < 4; p++) {
                xa[p]     = xc[(2 * s) * 16 + c * 4 + p];
                xa[p + 4] = xc[(2 * s + 1) * 16 + c * 4 + p];
            }
            float dv[4] = {0, 0, 0, 0}, sv[4] = {0, 0, 0, 0};
#pragma unroll
            for (int p = 0; p < 8; p++) {
                float xv = xa[p];
#pragma unroll
                for (int j = 0; j < 4; j++) {
                    dv[j] += xv * fl[p * 4 + j];
                    sv[j] += xv * fl[32 + p * 4 + j];
                }
            }
#pragma unroll
            for (int j = 0; j < 4; j++) {
                D[s * 16 + c * 4 + j]  = dv[j];
                xn[s * 16 + c * 4 + j] = sv[j];
            }
        }
        __syncthreads();
        int l = (m / 2 + 1 < 64) ? m / 2 + 1 : 64;
        for (int it = tid; it < 2 * l * 16; it += 256) {
            int i = it & 15;
            int f = (it >> 4) % l;
            int arr = it / (16 * l);
            const float* src = arr ? xn : D;
            float re = 0.f, im = 0.f;
            for (int t = 0; t < m; t++) {
                float v = src[t * 16 + i];
                re += v * g_tabc[(t * stride) * 64 + f];
                im -= v * g_tabs[(t * stride) * 64 + f];
            }
            SP[((arr * 64 + f) * 2 + 0) * 16 + i] = re;
            SP[((arr * 64 + f) * 2 + 1) * 16 + i] = im;
        }
        __syncthreads();
        for (int it = tid; it < 2 * l * 16; it += 256) {
            int o = it & 15;
            int f = (it >> 4) % l;
            int arr = it / (16 * l);
            float r = 0.f, q = 0.f;
            if (arr == 0) {
#pragma unroll 4
                for (int i2 = 0; i2 < 16; i2++) {
                    float Dr = SP[((0 * 64 + f) * 2 + 0) * 16 + i2];
                    float Di = SP[((0 * 64 + f) * 2 + 1) * 16 + i2];
                    float Xr = SP[((1 * 64 + f) * 2 + 0) * 16 + i2];
                    float Xi = SP[((1 * 64 + f) * 2 + 1) * 16 + i2];
                    float ar = g_wT[0 * 16384 + f * 256 + i2 * 16 + o];
                    float ai = g_wT[1 * 16384 + f * 256 + i2 * 16 + o];
                    float br = g_wT[2 * 16384 + f * 256 + i2 * 16 + o];
                    float bi = g_wT[3 * 16384 + f * 256 + i2 * 16 + o];
                    r += Dr * ar - Di * ai + Xr * br - Xi * bi;
                    q += Dr * ai + Di * ar + Xr * bi + Xi * br;
                }
            } else {
#pragma unroll 4
                for (int i2 = 0; i2 < 16; i2++) {
                    float Dr = SP[((0 * 64 + f) * 2 + 0) * 16 + i2];
                    float Di = SP[((0 * 64 + f) * 2 + 1) * 16 + i2];
                    float cr = g_wT[4 * 16384 + f * 256 + i2 * 16 + o];
                    float ci = g_wT[5 * 16384 + f * 256 + i2 * 16 + o];
                    r += Dr * cr - Di * ci;
                    q += Dr * ci + Di * cr;
                }
            }
            float wf = (f == 0 || 2 * f == m) ? (1.0f / (float)m) : (2.0f / (float)m);
            MS[((arr * 64 + f) * 2 + 0) * 16 + o] = r * wf;
            MS[((arr * 64 + f) * 2 + 1) * 16 + o] = q * wf;
        }
        __syncthreads();
        for (int it = tid; it < 2 * m * 16; it += 256) {
            int o = it & 15;
            int t = (it >> 4) % m;
            int arr = it / (16 * m);
            float acc = 0.f;
            for (int f = 0; f < l; f++) {
                float r = MS[((arr * 64 + f) * 2 + 0) * 16 + o];
                float q = MS[((arr * 64 + f) * 2 + 1) * 16 + o];
                acc += r * g_tabc[(t * stride) * 64 + f] - q * g_tabs[(t * stride) * 64 + f];
            }
            (arr ? US : UD)[(loff[li] + t) * 16 + o] = acc;
        }
        __syncthreads();
        float* tmp = xc; xc = xn; xn = tmp;
    }
    if (tid < 16) {
        int c = tid >> 2, o = tid & 3;
        float acc = fl[144 + o];
#pragma unroll
        for (int p = 0; p < 4; p++) acc += xc[c * 4 + p] * fl[128 + o * 4 + p];
        xn[tid] = acc;
    }
    __syncthreads();
    { float* tmp = xc; xc = xn; xn = tmp; }
    for (int li = 7; li >= 0; li--) {
        int m = 128 >> li;
        for (int it = tid; it < m * 4; it += 256) {
            int c = it & 3, s = it >> 2;
            float xs[4], ud[4];
#pragma unroll
            for (int j = 0; j < 4; j++) {
                xs[j] = xc[s * 16 + c * 4 + j] + US[(loff[li] + s) * 16 + c * 4 + j];
                ud[j] = UD[(loff[li] + s) * 16 + c * 4 + j];
            }
            float e[4] = {0, 0, 0, 0}, o4[4] = {0, 0, 0, 0};
#pragma unroll
            for (int p = 0; p < 4; p++)
#pragma unroll
                for (int j = 0; j < 4; j++) {
                    e[j]  += xs[p] * fl[64 + p * 4 + j] + ud[p] * fl[64 + (p + 4) * 4 + j];
                    o4[j] += xs[p] * fl[96 + p * 4 + j] + ud[p] * fl[96 + (p + 4) * 4 + j];
                }
#pragma unroll
            for (int j = 0; j < 4; j++) {
                xn[(2 * s) * 16 + c * 4 + j]     = e[j];
                xn[(2 * s + 1) * 16 + c * 4 + j] = o4[j];
            }
        }
        __syncthreads();
        float* tmp = xc; xc = xn; xn = tmp;
    }
    for (int i = tid; i < 4096; i += 256) xout[(size_t)b * 4096 + i] = xc[i];
}

// ---------------- reconstruction step (levels 0-5) ----------------
__global__ void recon_kernel(const float* __restrict__ xin, const float* __restrict__ Ud,
                             const float* __restrict__ Us, const float* __restrict__ rce,
                             const float* __restrict__ rco, float* __restrict__ out, int m) {
    __shared__ float se[32], so[32];
    int tid = threadIdx.x;
    if (tid < 32)      se[tid]      = rce[tid];
    else if (tid < 64) so[tid - 32] = rco[tid - 32];
    __syncthreads();
    int idx = blockIdx.x * blockDim.x + tid;
    if (idx >= BB * m * 4) return;
    int c = idx & 3;
    int s = (idx >> 2) % m;
    int b = idx / (m * 4);
    size_t r = ((size_t)b * m + s) * 16 + c * 4;
    float4 xv = *(const float4*)&xin[r];
    float4 uv = *(const float4*)&Us[r];
    float4 dv = *(const float4*)&Ud[r];
    float xs[4] = {xv.x + uv.x, xv.y + uv.y, xv.z + uv.z, xv.w + uv.w};
    float ud[4] = {dv.x, dv.y, dv.z, dv.w};
    float e[4] = {0, 0, 0, 0}, o[4] = {0, 0, 0, 0};
#pragma unroll
    for (int p = 0; p < 4; p++)
#pragma unroll
        for (int j = 0; j < 4; j++) {
            e[j] += xs[p] * se[p * 4 + j] + ud[p] * se[(p + 4) * 4 + j];
            o[j] += xs[p] * so[p * 4 + j] + ud[p] * so[(p + 4) * 4 + j];
        }
    size_t w = ((size_t)b * 2 * m + 2 * s) * 16 + c * 4;
    *(float4*)&out[w]      = make_float4(e[0], e[1], e[2], e[3]);
    *(float4*)&out[w + 16] = make_float4(o[0], o[1], o[2], o[3]);
}

// ---------------- side streams + events (host objects, created once) ----------------
struct SideStreams {
    cudaStream_t sB = nullptr, sC = nullptr;
    cudaEvent_t evRoot = nullptr, evB = nullptr, evD = nullptr, evC = nullptr,
                evMix = nullptr, evI1 = nullptr, evR = nullptr;
    void ensure() {
        if (sB) return;
        cudaStreamCreateWithFlags(&sB, cudaStreamNonBlocking);
        cudaStreamCreateWithFlags(&sC, cudaStreamNonBlocking);
        cudaEventCreateWithFlags(&evRoot, cudaEventDisableTiming);
        cudaEventCreateWithFlags(&evB,    cudaEventDisableTiming);
        cudaEventCreateWithFlags(&evD,    cudaEventDisableTiming);
        cudaEventCreateWithFlags(&evC,    cudaEventDisableTiming);
        cudaEventCreateWithFlags(&evMix,  cudaEventDisableTiming);
        cudaEventCreateWithFlags(&evI1,   cudaEventDisableTiming);
        cudaEventCreateWithFlags(&evR,    cudaEventDisableTiming);
    }
};
static SideStreams g_ss;

// ---------------- host orchestration ----------------
extern "C" void kernel_launch(void* const* d_in, const int* in_sizes, int n_in,
                              void* d_out, int out_size) {
    const float* x_in = (const float*)d_in[0];
    const float* ec_s = (const float*)d_in[1];
    const float* ec_d = (const float*)d_in[2];
    const float* rc_e = (const float*)d_in[3];
    const float* rc_o = (const float*)d_in[4];
    const float* t0_w = (const float*)d_in[5];
    const float* t0_b = (const float*)d_in[6];

    g_ss.ensure();

    const int DFWD_SM = 20480 * 4;
    const int INV_SM  = (16384 + 2048) * 4;
    const int DEEP_SM = (4096 + 4096 + 2048 + 4080 + 4080 + 4096 + 4096) * 4;
    cudaFuncSetAttribute(dfwd_kernel, cudaFuncAttributeMaxDynamicSharedMemorySize, DFWD_SM);
    cudaFuncSetAttribute(inv4_kernel, cudaFuncAttributeMaxDynamicSharedMemorySize, INV_SM);
    cudaFuncSetAttribute(deep_kernel, cudaFuncAttributeMaxDynamicSharedMemorySize, DEEP_SM);

    float *px0, *px1, *pd, *pUd, *pUs;
    cudaGetSymbolAddress((void**)&px0, g_x0);
    cudaGetSymbolAddress((void**)&px1, g_x1);
    cudaGetSymbolAddress((void**)&pd,  g_d);
    cudaGetSymbolAddress((void**)&pUd, g_Ud);
    cudaGetSymbolAddress((void**)&pUs, g_Us);

    // ---- fork stream B at root: full tab_row (deep only) + wprep ----
    cudaEventRecord(g_ss.evRoot, 0);
    cudaStreamWaitEvent(g_ss.sB, g_ss.evRoot, 0);
    tab_row_kernel<<<2048, 256, 0, g_ss.sB>>>();
    wprep_kernel<<<(6 * 16384 + 255) / 256, 256, 0, g_ss.sB>>>(
        (const float*)d_in[7], (const float*)d_in[8], (const float*)d_in[9],
        (const float*)d_in[10], (const float*)d_in[11], (const float*)d_in[12]);
    cudaEventRecord(g_ss.evB, g_ss.sB);

    // ---- main stream: quarter twiddle tables, then dfwd chain (levels 0..5) ----
    tab_rowP_kernel<<<512, 256>>>();

    float* xb[2] = {px0, px1};
    const int nchunks[6] = {32, 16, 8, 8, 4, 2};
    const int choffs[6]  = {0, 32, 48, 56, 64, 68};
    size_t offs[6];
    size_t off = 0;
    const float* src = x_in;

    for (int lev = 0; lev < 6; lev++) {
        int m = NN >> (lev + 1);
        offs[lev] = off;
        int stride = MAXM / m;
        float* xnext = xb[lev & 1];
        dfwd_kernel<<<dim3(8, nchunks[lev]), 256, DFWD_SM>>>(
            src, xnext, ec_d, ec_s, m, stride, nchunks[lev], choffs[lev], lev);
        off += m;
        src = xnext;
    }

    // ---- fork stream C: deep_kernel ----
    cudaEventRecord(g_ss.evD, 0);
    cudaStreamWaitEvent(g_ss.sC, g_ss.evD, 0);
    cudaStreamWaitEvent(g_ss.sC, g_ss.evB, 0);
    deep_kernel<<<BB, 256, DEEP_SM, g_ss.sC>>>(src, pd, ec_d, ec_s, rc_e, rc_o, t0_w, t0_b);
    cudaEventRecord(g_ss.evC, g_ss.sC);

    // ---- main: mix, edge4 on B, inv4 levels 1-5 ----
    cudaStreamWaitEvent(0, g_ss.evB, 0);
    mix_kernel<<<dim3(8, BB, 6), 256>>>();
    cudaEventRecord(g_ss.evMix, 0);
    cudaStreamWaitEvent(g_ss.sB, g_ss.evMix, 0);
    edge4_kernel<<<dim3(6, BB), 32, 0, g_ss.sB>>>(pUd, pUs);

    inv4_kernel<<<dim3(62, 8), 256, INV_SM>>>(pUd, pUs, 64);   // levels 1..5
    cudaEventRecord(g_ss.evI1, 0);

    // ---- recon levels 5..1 on stream B, concurrent with inv4 level 0 ----
    cudaStreamWaitEvent(g_ss.sB, g_ss.evI1, 0);
    cudaStreamWaitEvent(g_ss.sB, g_ss.evC, 0);
    const float* curx = pd;
    int flip = 0;
    for (int lev = 5; lev >= 1; lev--) {
        int m = NN >> (lev + 1);
        float* dst = xb[flip];
        int total = BB * m * 4;
        recon_kernel<<<(total + 255) / 256, 256, 0, g_ss.sB>>>(
            curx, pUd + (size_t)BB * CKD * offs[lev], pUs + (size_t)BB * CKD * offs[lev],
            rc_e, rc_o, dst, m);
        curx = dst;
        flip ^= 1;
    }
    cudaEventRecord(g_ss.evR, g_ss.sB);

    // ---- main: inv4 level 0 (64 tiles), then final recon ----
    inv4_kernel<<<dim3(64, 8), 256, INV_SM>>>(pUd, pUs, 0);
    cudaStreamWaitEvent(0, g_ss.evR, 0);
    {
        int m = NN >> 1;
        int total = BB * m * 4;
        recon_kernel<<<(total + 255) / 256, 256>>>(
            curx, pUd + (size_t)BB * CKD * offs[0], pUs + (size_t)BB * CKD * offs[0],
            rc_e, rc_o, (float*)d_out, m);
    }
}